// round 14
// baseline (speedup 1.0000x reference)
#include <cuda_runtime.h>
#include <cstdint>
#include <math.h>

#define T_STEPS 2048
#define BATCH   512
#define DIM     128
#define HID     128
#define NG      32          // 4 gates * 8 wires
#define CH      128         // real steps per chunk
#define WU      48          // warm-up steps (0.7311^48 ~ 3e-7 contraction)
#define NCH     (T_STEPS / CH)   // 16 chunks per sample
// smem: Xs(128*132) | Ws(32*132) | bs(32) | sPC(128) | sPS(128)  (~85.6KB, 2 blocks/SM)
#define GEMM_SMEM_FLOATS (128 * 132 + 32 * 132 + 32 + 128 + 128)
#define GEMM_SMEM_BYTES  (GEMM_SMEM_FLOATS * 4)

__device__ float g_A[(size_t)T_STEPS * BATCH * NG];   // poly coeffs [row][gate][8]
__device__ float g_PC[4][8][4];   // [jj][w][g] coeff of cos(z_w) in a_{2jj}
__device__ float g_PS[4][8][4];   // [jj][w][g] coeff of sin(z_w) in a_{2jj+1}

typedef unsigned long long u64;

// Chebyshev nodes xk = 0.75*cos((2k+1)pi/16), hardcoded (no runtime fp64 trig)
__device__ __constant__ double c_xk[8] = {
     0.73558896030242283695,  0.62360220922690892768,
     0.41667767476470166891,  0.14631774151209620177,
    -0.14631774151209620177, -0.41667767476470166891,
    -0.62360220922690892768, -0.73558896030242283695
};

__device__ __forceinline__ float tanh_fast(float x) {
    float r; asm("tanh.approx.f32 %0, %1;" : "=f"(r) : "f"(x)); return r;
}
// round fp32 -> tf32 (RNA), value stays a valid fp32 with low mantissa zeroed
__device__ __forceinline__ float tf32r(float x) {
    uint32_t u; asm("cvt.rna.tf32.f32 %0, %1;" : "=r"(u) : "f"(x));
    return __uint_as_float(u);
}
__device__ __forceinline__ void mma_tf32(float* c, uint32_t a0, uint32_t a1,
                                         uint32_t a2, uint32_t a3,
                                         uint32_t b0, uint32_t b1) {
    asm volatile(
        "mma.sync.aligned.m16n8k8.row.col.f32.tf32.tf32.f32 "
        "{%0,%1,%2,%3}, {%4,%5,%6,%7}, {%8,%9}, {%0,%1,%2,%3};"
        : "+f"(c[0]), "+f"(c[1]), "+f"(c[2]), "+f"(c[3])
        : "r"(a0), "r"(a1), "r"(a2), "r"(a3), "r"(b0), "r"(b1));
}

// ---------------- init: whsum + Lagrange-on-Chebyshev coefficient tables ----------------
__global__ void __launch_bounds__(1024) init_kernel(
        const float* __restrict__ Wf, const float* __restrict__ Wi,
        const float* __restrict__ Wu, const float* __restrict__ Wo) {
    __shared__ float  swh[32];
    __shared__ double sL[8][8];        // [node k][monomial j]
    const int tid = threadIdx.x;
    const int warp = tid >> 5, lane = tid & 31;

    // Phase 1: whsum (row sums of the H-part), one warp per (gate, wire)
    {
        const int g = warp >> 3, w = warp & 7;
        const float* W = (g == 0) ? Wf : (g == 1) ? Wi : (g == 2) ? Wu : Wo;
        const float4 v = *(const float4*)(W + w * (DIM + HID) + DIM + lane * 4);
        float s = (v.x + v.y) + (v.z + v.w);
        s += __shfl_xor_sync(0xffffffffu, s, 1);
        s += __shfl_xor_sync(0xffffffffu, s, 2);
        s += __shfl_xor_sync(0xffffffffu, s, 4);
        s += __shfl_xor_sync(0xffffffffu, s, 8);
        s += __shfl_xor_sync(0xffffffffu, s, 16);
        if (lane == 0) swh[warp] = s;
    }

    // Phase 2: Lagrange basis L_n -> monomial coeffs (threads 0..7; ONE fp64 divide)
    if (tid < 8) {
        const int n = tid;
        double cf[8];
        for (int i = 0; i < 8; i++) cf[i] = 0.0;
        cf[0] = 1.0;
        double den = 1.0;
        int deg = 0;
        for (int j = 0; j < 8; j++) {
            if (j == n) continue;
            for (int i = deg + 1; i >= 1; i--) cf[i] = cf[i - 1] - c_xk[j] * cf[i];
            cf[0] = -c_xk[j] * cf[0];
            deg++;
            den *= (c_xk[n] - c_xk[j]);
        }
        const double inv = 1.0 / den;    // 1 DDIV instead of 8
        for (int j = 0; j < 8; j++) sL[n][j] = cf[j] * inv;
    }
    __syncthreads();

    // Phase 3: one thread per (n, jj): 8 float cos + 8 float sin, double accumulate
    if (tid < 128) {
        const int n  = tid >> 2;       // 0..31
        const int jj = tid & 3;
        const int g = n >> 3, w = n & 7;
        const double s = (double)swh[n];
        const double m = (g == 2) ? (1.0 / 16.0) : (1.0 / 32.0);
        double pc = 0.0, ps = 0.0;
#pragma unroll
        for (int k = 0; k < 8; k++) {
            float th = (float)(s * c_xk[k]);
            pc += sL[k][2 * jj]     * (double)cosf(th);
            ps += sL[k][2 * jj + 1] * (double)sinf(th);
        }
        g_PC[jj][w][g] = (float)(-m * pc);
        g_PS[jj][w][g] = (float)( m * ps);
    }
}

// ---------------- GEMM (tf32 mma.sync) + fused eval, direct coefficient stores ----------------
// R13 skeleton; change: eval writes float4 coefficients DIRECTLY to g_A.
// A tid-quad (g=0..3, same r0) covers one contiguous 128B row segment, so the
// direct store is already fully coalesced — the As smem staging was pure overhead.
__global__ void __launch_bounds__(256, 2) gemm_kernel(
    const float* __restrict__ X,
    const float* __restrict__ Wf, const float* __restrict__ bf,
    const float* __restrict__ Wi, const float* __restrict__ bi,
    const float* __restrict__ Wu, const float* __restrict__ bu,
    const float* __restrict__ Wo, const float* __restrict__ bo) {
    extern __shared__ float sm[];
    float* Xs  = sm;                       // [128][132]
    float* Ws  = sm + 128 * 132;           // [32][132]  (pitch 132: conflict-free frags)
    float* bs  = Ws + 32 * 132;            // [32]
    float* sPC = bs + 32;                  // [4][8][4]
    float* sPS = sPC + 128;                // [4][8][4]
    float* Zs  = sm;                       // reuse Xs region, pitch 36
    const int tid = threadIdx.x;
    const size_t m0 = (size_t)blockIdx.x * 128;

    if (tid < 128)      sPC[tid] = ((const float*)g_PC)[tid];
    else                sPS[tid - 128] = ((const float*)g_PS)[tid - 128];

#pragma unroll
    for (int i = 0; i < 16; i++) {
        int idx = tid + i * 256;
        int n = idx >> 7, k = idx & 127;
        int g = n >> 3, w = n & 7;
        const float* W = (g == 0) ? Wf : (g == 1) ? Wi : (g == 2) ? Wu : Wo;
        Ws[n * 132 + k] = tf32r(W[w * 256 + k]);
    }
    if (tid < 32) {
        int g = tid >> 3, w = tid & 7;
        const float* bb = (g == 0) ? bf : (g == 1) ? bi : (g == 2) ? bu : bo;
        bs[tid] = bb[w];
    }
#pragma unroll
    for (int i = 0; i < 16; i++) {
        int idx = tid + i * 256;
        int m = idx >> 5, j = idx & 31;
        float4 v = *(const float4*)(X + (m0 + m) * 128 + j * 4);
        v.x = tf32r(v.x); v.y = tf32r(v.y); v.z = tf32r(v.z); v.w = tf32r(v.w);
        *(float4*)(Xs + m * 132 + j * 4) = v;
    }
    __syncthreads();

    const int lane = tid & 31;
    const int wq  = tid >> 5;
    const int gid = lane >> 2;
    const int t4  = lane & 3;
    const int ar0 = wq * 16 + gid;         // A row (and +8)

    float acc[4][4];
#pragma unroll
    for (int nt = 0; nt < 4; nt++)
#pragma unroll
        for (int i = 0; i < 4; i++) acc[nt][i] = 0.f;

#pragma unroll
    for (int kt = 0; kt < 16; kt++) {
        const int k0 = kt * 8;
        uint32_t a0 = __float_as_uint(Xs[ar0 * 132 + k0 + t4]);
        uint32_t a1 = __float_as_uint(Xs[(ar0 + 8) * 132 + k0 + t4]);
        uint32_t a2 = __float_as_uint(Xs[ar0 * 132 + k0 + t4 + 4]);
        uint32_t a3 = __float_as_uint(Xs[(ar0 + 8) * 132 + k0 + t4 + 4]);
#pragma unroll
        for (int nt = 0; nt < 4; nt++) {
            uint32_t b0 = __float_as_uint(Ws[(nt * 8 + gid) * 132 + k0 + t4]);
            uint32_t b1 = __float_as_uint(Ws[(nt * 8 + gid) * 132 + k0 + t4 + 4]);
            mma_tf32(acc[nt], a0, a1, a2, a3, b0, b1);
        }
    }
    __syncthreads();   // Xs reads done; reuse region as Zs staging

    // stage Z (with bias) into Zs, pitch 36, per the C-fragment layout
#pragma unroll
    for (int nt = 0; nt < 4; nt++) {
        const int col = nt * 8 + t4 * 2;
        const float bx = bs[col], by = bs[col + 1];
        *(float2*)(Zs + ar0 * 36 + col)       = make_float2(acc[nt][0] + bx, acc[nt][1] + by);
        *(float2*)(Zs + (ar0 + 8) * 36 + col) = make_float2(acc[nt][2] + bx, acc[nt][3] + by);
    }
    __syncthreads();

    // fused eval: thread -> (gate g, rows r0, r0+1); store coeffs straight to g_A
    {
        const int g = tid & 3;
        const int r0 = (tid >> 2) * 2;
        const float off = (g == 2) ? 0.5f : 0.25f;
#pragma unroll
        for (int rr = 0; rr < 2; rr++) {
            const int r = r0 + rr;
            float ca[8], sa[8];
#pragma unroll
            for (int w = 0; w < 8; w++) {
                float z = Zs[r * 36 + g * 8 + w];
                ca[w] = __cosf(z); sa[w] = __sinf(z);
            }
            float ae[4] = {off, 0.f, 0.f, 0.f}, ao[4] = {0.f, 0.f, 0.f, 0.f};
#pragma unroll
            for (int w = 0; w < 8; w++)
#pragma unroll
                for (int jj = 0; jj < 4; jj++) {
                    ae[jj] = fmaf(ca[w], sPC[(jj * 8 + w) * 4 + g], ae[jj]);
                    ao[jj] = fmaf(sa[w], sPS[(jj * 8 + w) * 4 + g], ao[jj]);
                }
            float4* dst = (float4*)(g_A + (m0 + r) * 32 + g * 8);
            dst[0] = make_float4(ae[0], ao[0], ae[1], ao[1]);
            dst[1] = make_float4(ae[2], ao[2], ae[3], ao[3]);
        }
    }
}

// ---------------- rnn_chunk: time-parallel chunks, CH=128 (UNCHANGED) ----------------
__global__ void __launch_bounds__(256) rnn_chunk_kernel(float* __restrict__ out) {
    const int wg = blockIdx.x * 8 + (threadIdx.x >> 5);
    const int b  = wg & (BATCH - 1);
    const int ct = wg >> 9;            // 0..NCH-1
    const int l  = threadIdx.x & 31;
    const int g  = l & 3;
    const float vm = (g == 2) ? 1.0f : 0.5f;
    const float va = (g == 2) ? 0.0f : 0.5f;

    const int t0 = ct * CH;
    const int tw = (t0 >= WU) ? (t0 - WU) : 0;
    const int total = t0 + CH - tw;    // 128 or 176
    const int skip  = t0 - tw;         // warm steps (0 or 48)

    const float* ap = g_A + ((size_t)tw * BATCH + b) * NG + g * 8;
    const size_t ASTR = (size_t)BATCH * NG;

    float4 p0[4], p1[4];
#pragma unroll
    for (int q = 0; q < 4; q++) {
        p0[q] = *(const float4*)(ap + (size_t)q * ASTR);
        p1[q] = *(const float4*)(ap + (size_t)q * ASTR + 4);
    }
    float s = 0.f, c = 0.f;
    for (int i0 = 0; i0 < total; i0 += 4) {
#pragma unroll
        for (int q = 0; q < 4; q++) {
            float4 A0 = p0[q], A1 = p1[q];
            int nx = i0 + 4 + q;
            if (nx < total) {
                p0[q] = *(const float4*)(ap + (size_t)nx * ASTR);
                p1[q] = *(const float4*)(ap + (size_t)nx * ASTR + 4);
            }
            // Estrin degree-7: coeffs a0..a7 = (A0.x..A0.w, A1.x..A1.w)
            float s2 = s * s, s4 = s2 * s2;
            float b0 = fmaf(A0.y, s, A0.x);
            float b1 = fmaf(A0.w, s, A0.z);
            float b2 = fmaf(A1.y, s, A1.x);
            float b3 = fmaf(A1.w, s, A1.z);
            float c0v = fmaf(b1, s2, b0);
            float c1v = fmaf(b3, s2, b2);
            float qv = fmaf(c1v, s4, c0v);
            float val = fmaf(vm, tanh_fast(qv), va);
            float f = __shfl_sync(0xffffffffu, val, 0);
            float i = __shfl_sync(0xffffffffu, val, 1);
            float u = __shfl_sync(0xffffffffu, val, 2);
            float o = __shfl_sync(0xffffffffu, val, 3);
            c = fmaf(f, c, i * u);
            s = o * tanh_fast(c);
            int it = i0 + q;
            if (it >= skip) {          // real step: store broadcast h row
                const size_t t = (size_t)(tw + it);
                float4 v = make_float4(s, s, s, s);
                *(float4*)(out + (t * BATCH + b) * HID + l * 4) = v;
            }
        }
    }
    if (ct == NCH - 1) {               // hx = h[T-1], cx = final c
        float4 vs = make_float4(s, s, s, s);
        *(float4*)(out + ((size_t)T_STEPS * BATCH + b) * HID + l * 4) = vs;
        float4 vc = make_float4(c, c, c, c);
        *(float4*)(out + ((size_t)T_STEPS * BATCH + BATCH + b) * HID + l * 4) = vc;
    }
}

extern "C" void kernel_launch(void* const* d_in, const int* in_sizes, int n_in,
                              void* d_out, int out_size) {
    const float* X  = (const float*)d_in[0];
    const float* Wf = (const float*)d_in[1];
    const float* bf = (const float*)d_in[2];
    const float* Wi = (const float*)d_in[3];
    const float* bi = (const float*)d_in[4];
    const float* Wu = (const float*)d_in[5];
    const float* bu = (const float*)d_in[6];
    const float* Wo = (const float*)d_in[7];
    const float* bo = (const float*)d_in[8];
    float* out = (float*)d_out;

    cudaFuncSetAttribute(gemm_kernel, cudaFuncAttributeMaxDynamicSharedMemorySize,
                         GEMM_SMEM_BYTES);

    init_kernel<<<1, 1024>>>(Wf, Wi, Wu, Wo);
    gemm_kernel<<<(T_STEPS * BATCH) / 128, 256, GEMM_SMEM_BYTES>>>(
        X, Wf, bf, Wi, bi, Wu, bu, Wo, bo);
    rnn_chunk_kernel<<<(BATCH * NCH) / 8, 256>>>(out);
}

// round 15
// speedup vs baseline: 1.0063x; 1.0063x over previous
#include <cuda_runtime.h>
#include <cstdint>
#include <math.h>

#define T_STEPS 2048
#define BATCH   512
#define DIM     128
#define HID     128
#define NG      32          // 4 gates * 8 wires
#define CH      128         // real steps per chunk
#define WU      48          // warm-up steps (0.7311^48 ~ 3e-7 contraction)
#define NCH     (T_STEPS / CH)   // 16 chunks per sample
// smem: Xs(128*132) | Ws(32*132) | bs(32) | sPC(128) | sPS(128)  (~85.6KB, 2 blocks/SM)
#define GEMM_SMEM_FLOATS (128 * 132 + 32 * 132 + 32 + 128 + 128)
#define GEMM_SMEM_BYTES  (GEMM_SMEM_FLOATS * 4)

__device__ float g_A[(size_t)T_STEPS * BATCH * NG];   // poly coeffs [row][gate][8]
__device__ float g_PC[4][8][4];   // [jj][w][g] coeff of cos(z_w) in a_{2jj}
__device__ float g_PS[4][8][4];   // [jj][w][g] coeff of sin(z_w) in a_{2jj+1}

typedef unsigned long long u64;

// Chebyshev nodes xk = 0.75*cos((2k+1)pi/16), hardcoded (no runtime fp64 trig)
__device__ __constant__ double c_xk[8] = {
     0.73558896030242283695,  0.62360220922690892768,
     0.41667767476470166891,  0.14631774151209620177,
    -0.14631774151209620177, -0.41667767476470166891,
    -0.62360220922690892768, -0.73558896030242283695
};

__device__ __forceinline__ float tanh_fast(float x) {
    float r; asm("tanh.approx.f32 %0, %1;" : "=f"(r) : "f"(x)); return r;
}
// round fp32 -> tf32 (RNA), value stays a valid fp32 with low mantissa zeroed
__device__ __forceinline__ float tf32r(float x) {
    uint32_t u; asm("cvt.rna.tf32.f32 %0, %1;" : "=r"(u) : "f"(x));
    return __uint_as_float(u);
}
__device__ __forceinline__ void mma_tf32(float* c, uint32_t a0, uint32_t a1,
                                         uint32_t a2, uint32_t a3,
                                         uint32_t b0, uint32_t b1) {
    asm volatile(
        "mma.sync.aligned.m16n8k8.row.col.f32.tf32.tf32.f32 "
        "{%0,%1,%2,%3}, {%4,%5,%6,%7}, {%8,%9}, {%0,%1,%2,%3};"
        : "+f"(c[0]), "+f"(c[1]), "+f"(c[2]), "+f"(c[3])
        : "r"(a0), "r"(a1), "r"(a2), "r"(a3), "r"(b0), "r"(b1));
}

// ---------------- init: whsum + Lagrange-on-Chebyshev coefficient tables ----------------
__global__ void __launch_bounds__(1024) init_kernel(
        const float* __restrict__ Wf, const float* __restrict__ Wi,
        const float* __restrict__ Wu, const float* __restrict__ Wo) {
    __shared__ float  swh[32];
    __shared__ double sL[8][8];        // [node k][monomial j]
    const int tid = threadIdx.x;
    const int warp = tid >> 5, lane = tid & 31;

    // Phase 1: whsum (row sums of the H-part), one warp per (gate, wire)
    {
        const int g = warp >> 3, w = warp & 7;
        const float* W = (g == 0) ? Wf : (g == 1) ? Wi : (g == 2) ? Wu : Wo;
        const float4 v = *(const float4*)(W + w * (DIM + HID) + DIM + lane * 4);
        float s = (v.x + v.y) + (v.z + v.w);
        s += __shfl_xor_sync(0xffffffffu, s, 1);
        s += __shfl_xor_sync(0xffffffffu, s, 2);
        s += __shfl_xor_sync(0xffffffffu, s, 4);
        s += __shfl_xor_sync(0xffffffffu, s, 8);
        s += __shfl_xor_sync(0xffffffffu, s, 16);
        if (lane == 0) swh[warp] = s;
    }

    // Phase 2: Lagrange basis L_n -> monomial coeffs (threads 0..7; ONE fp64 divide)
    if (tid < 8) {
        const int n = tid;
        double cf[8];
        for (int i = 0; i < 8; i++) cf[i] = 0.0;
        cf[0] = 1.0;
        double den = 1.0;
        int deg = 0;
        for (int j = 0; j < 8; j++) {
            if (j == n) continue;
            for (int i = deg + 1; i >= 1; i--) cf[i] = cf[i - 1] - c_xk[j] * cf[i];
            cf[0] = -c_xk[j] * cf[0];
            deg++;
            den *= (c_xk[n] - c_xk[j]);
        }
        const double inv = 1.0 / den;    // 1 DDIV instead of 8
        for (int j = 0; j < 8; j++) sL[n][j] = cf[j] * inv;
    }
    __syncthreads();

    // Phase 3: one thread per (n, jj): 8 float cos + 8 float sin, double accumulate
    if (tid < 128) {
        const int n  = tid >> 2;       // 0..31
        const int jj = tid & 3;
        const int g = n >> 3, w = n & 7;
        const double s = (double)swh[n];
        const double m = (g == 2) ? (1.0 / 16.0) : (1.0 / 32.0);
        double pc = 0.0, ps = 0.0;
#pragma unroll
        for (int k = 0; k < 8; k++) {
            float th = (float)(s * c_xk[k]);
            pc += sL[k][2 * jj]     * (double)cosf(th);
            ps += sL[k][2 * jj + 1] * (double)sinf(th);
        }
        g_PC[jj][w][g] = (float)(-m * pc);
        g_PS[jj][w][g] = (float)( m * ps);
    }
}

// ---------------- GEMM (tf32 mma.sync) + fused eval (R13-exact epilogue) ----------------
// Lesson R14: fragment-layout direct stores produce 32B-strided partial-sector
// writes; the As smem staging pass IS the coalescer. Only additions vs R13:
// __ldcs on X (read-once), __stcs on g_A (no L2 thrash).
__global__ void __launch_bounds__(256, 2) gemm_kernel(
    const float* __restrict__ X,
    const float* __restrict__ Wf, const float* __restrict__ bf,
    const float* __restrict__ Wi, const float* __restrict__ bi,
    const float* __restrict__ Wu, const float* __restrict__ bu,
    const float* __restrict__ Wo, const float* __restrict__ bo) {
    extern __shared__ float sm[];
    float* Xs  = sm;                       // [128][132]
    float* Ws  = sm + 128 * 132;           // [32][132]  (pitch 132: conflict-free frags)
    float* bs  = Ws + 32 * 132;            // [32]
    float* sPC = bs + 32;                  // [4][8][4]
    float* sPS = sPC + 128;                // [4][8][4]
    float* Zs  = sm;                       // reuse Xs region, pitch 36
    float* As  = sm + 4608;                // second half of Xs region, pitch 36
    const int tid = threadIdx.x;
    const size_t m0 = (size_t)blockIdx.x * 128;

    if (tid < 128)      sPC[tid] = ((const float*)g_PC)[tid];
    else                sPS[tid - 128] = ((const float*)g_PS)[tid - 128];

#pragma unroll
    for (int i = 0; i < 16; i++) {
        int idx = tid + i * 256;
        int n = idx >> 7, k = idx & 127;
        int g = n >> 3, w = n & 7;
        const float* W = (g == 0) ? Wf : (g == 1) ? Wi : (g == 2) ? Wu : Wo;
        Ws[n * 132 + k] = tf32r(W[w * 256 + k]);
    }
    if (tid < 32) {
        int g = tid >> 3, w = tid & 7;
        const float* bb = (g == 0) ? bf : (g == 1) ? bi : (g == 2) ? bu : bo;
        bs[tid] = bb[w];
    }
#pragma unroll
    for (int i = 0; i < 16; i++) {
        int idx = tid + i * 256;
        int m = idx >> 5, j = idx & 31;
        float4 v = __ldcs((const float4*)(X + (m0 + m) * 128 + j * 4));
        v.x = tf32r(v.x); v.y = tf32r(v.y); v.z = tf32r(v.z); v.w = tf32r(v.w);
        *(float4*)(Xs + m * 132 + j * 4) = v;
    }
    __syncthreads();

    const int lane = tid & 31;
    const int wq  = tid >> 5;
    const int gid = lane >> 2;
    const int t4  = lane & 3;
    const int ar0 = wq * 16 + gid;         // A row (and +8)

    float acc[4][4];
#pragma unroll
    for (int nt = 0; nt < 4; nt++)
#pragma unroll
        for (int i = 0; i < 4; i++) acc[nt][i] = 0.f;

#pragma unroll
    for (int kt = 0; kt < 16; kt++) {
        const int k0 = kt * 8;
        uint32_t a0 = __float_as_uint(Xs[ar0 * 132 + k0 + t4]);
        uint32_t a1 = __float_as_uint(Xs[(ar0 + 8) * 132 + k0 + t4]);
        uint32_t a2 = __float_as_uint(Xs[ar0 * 132 + k0 + t4 + 4]);
        uint32_t a3 = __float_as_uint(Xs[(ar0 + 8) * 132 + k0 + t4 + 4]);
#pragma unroll
        for (int nt = 0; nt < 4; nt++) {
            uint32_t b0 = __float_as_uint(Ws[(nt * 8 + gid) * 132 + k0 + t4]);
            uint32_t b1 = __float_as_uint(Ws[(nt * 8 + gid) * 132 + k0 + t4 + 4]);
            mma_tf32(acc[nt], a0, a1, a2, a3, b0, b1);
        }
    }
    __syncthreads();   // Xs reads done; reuse region as Zs staging

    // stage Z (with bias) into Zs, pitch 36, per the C-fragment layout
#pragma unroll
    for (int nt = 0; nt < 4; nt++) {
        const int col = nt * 8 + t4 * 2;
        const float bx = bs[col], by = bs[col + 1];
        *(float2*)(Zs + ar0 * 36 + col)       = make_float2(acc[nt][0] + bx, acc[nt][1] + by);
        *(float2*)(Zs + (ar0 + 8) * 36 + col) = make_float2(acc[nt][2] + bx, acc[nt][3] + by);
    }
    __syncthreads();

    // fused eval: thread -> (gate g, rows r0, r0+1), stage coeffs into As
    {
        const int g = tid & 3;
        const int r0 = (tid >> 2) * 2;
        const float off = (g == 2) ? 0.5f : 0.25f;
#pragma unroll
        for (int rr = 0; rr < 2; rr++) {
            const int r = r0 + rr;
            float ca[8], sa[8];
#pragma unroll
            for (int w = 0; w < 8; w++) {
                float z = Zs[r * 36 + g * 8 + w];
                ca[w] = __cosf(z); sa[w] = __sinf(z);
            }
            float ae[4] = {off, 0.f, 0.f, 0.f}, ao[4] = {0.f, 0.f, 0.f, 0.f};
#pragma unroll
            for (int w = 0; w < 8; w++)
#pragma unroll
                for (int jj = 0; jj < 4; jj++) {
                    ae[jj] = fmaf(ca[w], sPC[(jj * 8 + w) * 4 + g], ae[jj]);
                    ao[jj] = fmaf(sa[w], sPS[(jj * 8 + w) * 4 + g], ao[jj]);
                }
            float4* dst = (float4*)(As + r * 36 + g * 8);
            dst[0] = make_float4(ae[0], ao[0], ae[1], ao[1]);
            dst[1] = make_float4(ae[2], ao[2], ae[3], ao[3]);
        }
    }
    __syncthreads();
    // coalesced store As -> g_A (1024 float4), streaming (read once, much later)
#pragma unroll
    for (int i = 0; i < 4; i++) {
        int idx = tid + i * 256;
        int m = idx >> 3, q = idx & 7;
        float4 v = *(const float4*)(As + m * 36 + q * 4);
        __stcs((float4*)(g_A + (m0 + m) * 32 + q * 4), v);
    }
}

// ---------------- rnn_chunk: time-parallel chunks, CH=128 ----------------
__global__ void __launch_bounds__(256) rnn_chunk_kernel(float* __restrict__ out) {
    const int wg = blockIdx.x * 8 + (threadIdx.x >> 5);
    const int b  = wg & (BATCH - 1);
    const int ct = wg >> 9;            // 0..NCH-1
    const int l  = threadIdx.x & 31;
    const int g  = l & 3;
    const float vm = (g == 2) ? 1.0f : 0.5f;
    const float va = (g == 2) ? 0.0f : 0.5f;

    const int t0 = ct * CH;
    const int tw = (t0 >= WU) ? (t0 - WU) : 0;
    const int total = t0 + CH - tw;    // 128 or 176
    const int skip  = t0 - tw;         // warm steps (0 or 48)

    const float* ap = g_A + ((size_t)tw * BATCH + b) * NG + g * 8;
    const size_t ASTR = (size_t)BATCH * NG;

    float4 p0[4], p1[4];
#pragma unroll
    for (int q = 0; q < 4; q++) {
        p0[q] = *(const float4*)(ap + (size_t)q * ASTR);
        p1[q] = *(const float4*)(ap + (size_t)q * ASTR + 4);
    }
    float s = 0.f, c = 0.f;
    for (int i0 = 0; i0 < total; i0 += 4) {
#pragma unroll
        for (int q = 0; q < 4; q++) {
            float4 A0 = p0[q], A1 = p1[q];
            int nx = i0 + 4 + q;
            if (nx < total) {
                p0[q] = *(const float4*)(ap + (size_t)nx * ASTR);
                p1[q] = *(const float4*)(ap + (size_t)nx * ASTR + 4);
            }
            // Estrin degree-7: coeffs a0..a7 = (A0.x..A0.w, A1.x..A1.w)
            float s2 = s * s, s4 = s2 * s2;
            float b0 = fmaf(A0.y, s, A0.x);
            float b1 = fmaf(A0.w, s, A0.z);
            float b2 = fmaf(A1.y, s, A1.x);
            float b3 = fmaf(A1.w, s, A1.z);
            float c0v = fmaf(b1, s2, b0);
            float c1v = fmaf(b3, s2, b2);
            float qv = fmaf(c1v, s4, c0v);
            float val = fmaf(vm, tanh_fast(qv), va);
            float f = __shfl_sync(0xffffffffu, val, 0);
            float i = __shfl_sync(0xffffffffu, val, 1);
            float u = __shfl_sync(0xffffffffu, val, 2);
            float o = __shfl_sync(0xffffffffu, val, 3);
            c = fmaf(f, c, i * u);
            s = o * tanh_fast(c);
            int it = i0 + q;
            if (it >= skip) {          // real step: store broadcast h row (write-only)
                const size_t t = (size_t)(tw + it);
                float4 v = make_float4(s, s, s, s);
                __stcs((float4*)(out + (t * BATCH + b) * HID + l * 4), v);
            }
        }
    }
    if (ct == NCH - 1) {               // hx = h[T-1], cx = final c
        float4 vs = make_float4(s, s, s, s);
        __stcs((float4*)(out + ((size_t)T_STEPS * BATCH + b) * HID + l * 4), vs);
        float4 vc = make_float4(c, c, c, c);
        __stcs((float4*)(out + ((size_t)T_STEPS * BATCH + BATCH + b) * HID + l * 4), vc);
    }
}

extern "C" void kernel_launch(void* const* d_in, const int* in_sizes, int n_in,
                              void* d_out, int out_size) {
    const float* X  = (const float*)d_in[0];
    const float* Wf = (const float*)d_in[1];
    const float* bf = (const float*)d_in[2];
    const float* Wi = (const float*)d_in[3];
    const float* bi = (const float*)d_in[4];
    const float* Wu = (const float*)d_in[5];
    const float* bu = (const float*)d_in[6];
    const float* Wo = (const float*)d_in[7];
    const float* bo = (const float*)d_in[8];
    float* out = (float*)d_out;

    cudaFuncSetAttribute(gemm_kernel, cudaFuncAttributeMaxDynamicSharedMemorySize,
                         GEMM_SMEM_BYTES);

    init_kernel<<<1, 1024>>>(Wf, Wi, Wu, Wo);
    gemm_kernel<<<(T_STEPS * BATCH) / 128, 256, GEMM_SMEM_BYTES>>>(
        X, Wf, bf, Wi, bi, Wu, bu, Wo, bo);
    rnn_chunk_kernel<<<(BATCH * NCH) / 8, 256>>>(out);
}

// round 16
// speedup vs baseline: 1.0286x; 1.0221x over previous
#include <cuda_runtime.h>
#include <cstdint>
#include <math.h>

#define T_STEPS 2048
#define BATCH   512
#define DIM     128
#define HID     128
#define NG      32          // 4 gates * 8 wires
#define CH      128         // real steps per chunk
#define WU      48          // warm-up steps (0.7311^48 ~ 3e-7 contraction)
#define NCH     (T_STEPS / CH)   // 16 chunks per sample
// smem: Xs(128*132) | Ws(32*132) | bs(32) | sPC(128) | sPS(128)  (~85.6KB, 2 blocks/SM)
#define GEMM_SMEM_FLOATS (128 * 132 + 32 * 132 + 32 + 128 + 128)
#define GEMM_SMEM_BYTES  (GEMM_SMEM_FLOATS * 4)

__device__ float g_A[(size_t)T_STEPS * BATCH * NG];   // poly coeffs [row][gate][8]
__device__ float g_PC[4][8][4];   // [jj][w][g] coeff of cos(z_w) in a_{2jj}
__device__ float g_PS[4][8][4];   // [jj][w][g] coeff of sin(z_w) in a_{2jj+1}

typedef unsigned long long u64;

// Chebyshev nodes xk = 0.75*cos((2k+1)pi/16), hardcoded (no runtime fp64 trig)
__device__ __constant__ double c_xk[8] = {
     0.73558896030242283695,  0.62360220922690892768,
     0.41667767476470166891,  0.14631774151209620177,
    -0.14631774151209620177, -0.41667767476470166891,
    -0.62360220922690892768, -0.73558896030242283695
};

__device__ __forceinline__ float tanh_fast(float x) {
    float r; asm("tanh.approx.f32 %0, %1;" : "=f"(r) : "f"(x)); return r;
}
// round fp32 -> tf32 (RNA), value stays a valid fp32 with low mantissa zeroed
__device__ __forceinline__ float tf32r(float x) {
    uint32_t u; asm("cvt.rna.tf32.f32 %0, %1;" : "=r"(u) : "f"(x));
    return __uint_as_float(u);
}
__device__ __forceinline__ void mma_tf32(float* c, uint32_t a0, uint32_t a1,
                                         uint32_t a2, uint32_t a3,
                                         uint32_t b0, uint32_t b1) {
    asm volatile(
        "mma.sync.aligned.m16n8k8.row.col.f32.tf32.tf32.f32 "
        "{%0,%1,%2,%3}, {%4,%5,%6,%7}, {%8,%9}, {%0,%1,%2,%3};"
        : "+f"(c[0]), "+f"(c[1]), "+f"(c[2]), "+f"(c[3])
        : "r"(a0), "r"(a1), "r"(a2), "r"(a3), "r"(b0), "r"(b1));
}

// ---------------- init: whsum + Lagrange-on-Chebyshev coefficient tables ----------------
__global__ void __launch_bounds__(1024) init_kernel(
        const float* __restrict__ Wf, const float* __restrict__ Wi,
        const float* __restrict__ Wu, const float* __restrict__ Wo) {
    __shared__ float  swh[32];
    __shared__ double sL[8][8];        // [node k][monomial j]
    const int tid = threadIdx.x;
    const int warp = tid >> 5, lane = tid & 31;

    // Phase 1: whsum (row sums of the H-part), one warp per (gate, wire)
    {
        const int g = warp >> 3, w = warp & 7;
        const float* W = (g == 0) ? Wf : (g == 1) ? Wi : (g == 2) ? Wu : Wo;
        const float4 v = *(const float4*)(W + w * (DIM + HID) + DIM + lane * 4);
        float s = (v.x + v.y) + (v.z + v.w);
        s += __shfl_xor_sync(0xffffffffu, s, 1);
        s += __shfl_xor_sync(0xffffffffu, s, 2);
        s += __shfl_xor_sync(0xffffffffu, s, 4);
        s += __shfl_xor_sync(0xffffffffu, s, 8);
        s += __shfl_xor_sync(0xffffffffu, s, 16);
        if (lane == 0) swh[warp] = s;
    }

    // Phase 2: Lagrange basis L_n -> monomial coeffs (threads 0..7; ONE fp64 divide)
    if (tid < 8) {
        const int n = tid;
        double cf[8];
        for (int i = 0; i < 8; i++) cf[i] = 0.0;
        cf[0] = 1.0;
        double den = 1.0;
        int deg = 0;
        for (int j = 0; j < 8; j++) {
            if (j == n) continue;
            for (int i = deg + 1; i >= 1; i--) cf[i] = cf[i - 1] - c_xk[j] * cf[i];
            cf[0] = -c_xk[j] * cf[0];
            deg++;
            den *= (c_xk[n] - c_xk[j]);
        }
        const double inv = 1.0 / den;    // 1 DDIV instead of 8
        for (int j = 0; j < 8; j++) sL[n][j] = cf[j] * inv;
    }
    __syncthreads();

    // Phase 3: one thread per (n, jj): 8 float cos + 8 float sin, double accumulate
    if (tid < 128) {
        const int n  = tid >> 2;       // 0..31
        const int jj = tid & 3;
        const int g = n >> 3, w = n & 7;
        const double s = (double)swh[n];
        const double m = (g == 2) ? (1.0 / 16.0) : (1.0 / 32.0);
        double pc = 0.0, ps = 0.0;
#pragma unroll
        for (int k = 0; k < 8; k++) {
            float th = (float)(s * c_xk[k]);
            pc += sL[k][2 * jj]     * (double)cosf(th);
            ps += sL[k][2 * jj + 1] * (double)sinf(th);
        }
        g_PC[jj][w][g] = (float)(-m * pc);
        g_PS[jj][w][g] = (float)( m * ps);
    }
}

// ---------------- GEMM (tf32 mma.sync) + fused eval (R13-exact; NO cache hints) ----------------
__global__ void __launch_bounds__(256, 2) gemm_kernel(
    const float* __restrict__ X,
    const float* __restrict__ Wf, const float* __restrict__ bf,
    const float* __restrict__ Wi, const float* __restrict__ bi,
    const float* __restrict__ Wu, const float* __restrict__ bu,
    const float* __restrict__ Wo, const float* __restrict__ bo) {
    extern __shared__ float sm[];
    float* Xs  = sm;                       // [128][132]
    float* Ws  = sm + 128 * 132;           // [32][132]  (pitch 132: conflict-free frags)
    float* bs  = Ws + 32 * 132;            // [32]
    float* sPC = bs + 32;                  // [4][8][4]
    float* sPS = sPC + 128;                // [4][8][4]
    float* Zs  = sm;                       // reuse Xs region, pitch 36
    float* As  = sm + 4608;                // second half of Xs region, pitch 36
    const int tid = threadIdx.x;
    const size_t m0 = (size_t)blockIdx.x * 128;

    if (tid < 128)      sPC[tid] = ((const float*)g_PC)[tid];
    else                sPS[tid - 128] = ((const float*)g_PS)[tid - 128];

#pragma unroll
    for (int i = 0; i < 16; i++) {
        int idx = tid + i * 256;
        int n = idx >> 7, k = idx & 127;
        int g = n >> 3, w = n & 7;
        const float* W = (g == 0) ? Wf : (g == 1) ? Wi : (g == 2) ? Wu : Wo;
        Ws[n * 132 + k] = tf32r(W[w * 256 + k]);
    }
    if (tid < 32) {
        int g = tid >> 3, w = tid & 7;
        const float* bb = (g == 0) ? bf : (g == 1) ? bi : (g == 2) ? bu : bo;
        bs[tid] = bb[w];
    }
#pragma unroll
    for (int i = 0; i < 16; i++) {
        int idx = tid + i * 256;
        int m = idx >> 5, j = idx & 31;
        float4 v = *(const float4*)(X + (m0 + m) * 128 + j * 4);
        v.x = tf32r(v.x); v.y = tf32r(v.y); v.z = tf32r(v.z); v.w = tf32r(v.w);
        *(float4*)(Xs + m * 132 + j * 4) = v;
    }
    __syncthreads();

    const int lane = tid & 31;
    const int wq  = tid >> 5;
    const int gid = lane >> 2;
    const int t4  = lane & 3;
    const int ar0 = wq * 16 + gid;         // A row (and +8)

    float acc[4][4];
#pragma unroll
    for (int nt = 0; nt < 4; nt++)
#pragma unroll
        for (int i = 0; i < 4; i++) acc[nt][i] = 0.f;

#pragma unroll
    for (int kt = 0; kt < 16; kt++) {
        const int k0 = kt * 8;
        uint32_t a0 = __float_as_uint(Xs[ar0 * 132 + k0 + t4]);
        uint32_t a1 = __float_as_uint(Xs[(ar0 + 8) * 132 + k0 + t4]);
        uint32_t a2 = __float_as_uint(Xs[ar0 * 132 + k0 + t4 + 4]);
        uint32_t a3 = __float_as_uint(Xs[(ar0 + 8) * 132 + k0 + t4 + 4]);
#pragma unroll
        for (int nt = 0; nt < 4; nt++) {
            uint32_t b0 = __float_as_uint(Ws[(nt * 8 + gid) * 132 + k0 + t4]);
            uint32_t b1 = __float_as_uint(Ws[(nt * 8 + gid) * 132 + k0 + t4 + 4]);
            mma_tf32(acc[nt], a0, a1, a2, a3, b0, b1);
        }
    }
    __syncthreads();   // Xs reads done; reuse region as Zs staging

    // stage Z (with bias) into Zs, pitch 36, per the C-fragment layout
#pragma unroll
    for (int nt = 0; nt < 4; nt++) {
        const int col = nt * 8 + t4 * 2;
        const float bx = bs[col], by = bs[col + 1];
        *(float2*)(Zs + ar0 * 36 + col)       = make_float2(acc[nt][0] + bx, acc[nt][1] + by);
        *(float2*)(Zs + (ar0 + 8) * 36 + col) = make_float2(acc[nt][2] + bx, acc[nt][3] + by);
    }
    __syncthreads();

    // fused eval: thread -> (gate g, rows r0, r0+1), stage coeffs into As
    {
        const int g = tid & 3;
        const int r0 = (tid >> 2) * 2;
        const float off = (g == 2) ? 0.5f : 0.25f;
#pragma unroll
        for (int rr = 0; rr < 2; rr++) {
            const int r = r0 + rr;
            float ca[8], sa[8];
#pragma unroll
            for (int w = 0; w < 8; w++) {
                float z = Zs[r * 36 + g * 8 + w];
                ca[w] = __cosf(z); sa[w] = __sinf(z);
            }
            float ae[4] = {off, 0.f, 0.f, 0.f}, ao[4] = {0.f, 0.f, 0.f, 0.f};
#pragma unroll
            for (int w = 0; w < 8; w++)
#pragma unroll
                for (int jj = 0; jj < 4; jj++) {
                    ae[jj] = fmaf(ca[w], sPC[(jj * 8 + w) * 4 + g], ae[jj]);
                    ao[jj] = fmaf(sa[w], sPS[(jj * 8 + w) * 4 + g], ao[jj]);
                }
            float4* dst = (float4*)(As + r * 36 + g * 8);
            dst[0] = make_float4(ae[0], ao[0], ae[1], ao[1]);
            dst[1] = make_float4(ae[2], ao[2], ae[3], ao[3]);
        }
    }
    __syncthreads();
    // coalesced store As -> g_A (1024 float4)
#pragma unroll
    for (int i = 0; i < 4; i++) {
        int idx = tid + i * 256;
        int m = idx >> 3, q = idx & 7;
        float4 v = *(const float4*)(As + m * 36 + q * 4);
        *(float4*)(g_A + (m0 + m) * 32 + q * 4) = v;
    }
}

// ---------------- rnn_chunk: time-parallel chunks, CH=128 (NO cache hints) ----------------
__global__ void __launch_bounds__(256) rnn_chunk_kernel(float* __restrict__ out) {
    const int wg = blockIdx.x * 8 + (threadIdx.x >> 5);
    const int b  = wg & (BATCH - 1);
    const int ct = wg >> 9;            // 0..NCH-1
    const int l  = threadIdx.x & 31;
    const int g  = l & 3;
    const float vm = (g == 2) ? 1.0f : 0.5f;
    const float va = (g == 2) ? 0.0f : 0.5f;

    const int t0 = ct * CH;
    const int tw = (t0 >= WU) ? (t0 - WU) : 0;
    const int total = t0 + CH - tw;    // 128 or 176
    const int skip  = t0 - tw;         // warm steps (0 or 48)

    const float* ap = g_A + ((size_t)tw * BATCH + b) * NG + g * 8;
    const size_t ASTR = (size_t)BATCH * NG;

    float4 p0[4], p1[4];
#pragma unroll
    for (int q = 0; q < 4; q++) {
        p0[q] = *(const float4*)(ap + (size_t)q * ASTR);
        p1[q] = *(const float4*)(ap + (size_t)q * ASTR + 4);
    }
    float s = 0.f, c = 0.f;
    for (int i0 = 0; i0 < total; i0 += 4) {
#pragma unroll
        for (int q = 0; q < 4; q++) {
            float4 A0 = p0[q], A1 = p1[q];
            int nx = i0 + 4 + q;
            if (nx < total) {
                p0[q] = *(const float4*)(ap + (size_t)nx * ASTR);
                p1[q] = *(const float4*)(ap + (size_t)nx * ASTR + 4);
            }
            // Estrin degree-7: coeffs a0..a7 = (A0.x..A0.w, A1.x..A1.w)
            float s2 = s * s, s4 = s2 * s2;
            float b0 = fmaf(A0.y, s, A0.x);
            float b1 = fmaf(A0.w, s, A0.z);
            float b2 = fmaf(A1.y, s, A1.x);
            float b3 = fmaf(A1.w, s, A1.z);
            float c0v = fmaf(b1, s2, b0);
            float c1v = fmaf(b3, s2, b2);
            float qv = fmaf(c1v, s4, c0v);
            float val = fmaf(vm, tanh_fast(qv), va);
            float f = __shfl_sync(0xffffffffu, val, 0);
            float i = __shfl_sync(0xffffffffu, val, 1);
            float u = __shfl_sync(0xffffffffu, val, 2);
            float o = __shfl_sync(0xffffffffu, val, 3);
            c = fmaf(f, c, i * u);
            s = o * tanh_fast(c);
            int it = i0 + q;
            if (it >= skip) {          // real step: store broadcast h row
                const size_t t = (size_t)(tw + it);
                float4 v = make_float4(s, s, s, s);
                *(float4*)(out + (t * BATCH + b) * HID + l * 4) = v;
            }
        }
    }
    if (ct == NCH - 1) {               // hx = h[T-1], cx = final c
        float4 vs = make_float4(s, s, s, s);
        *(float4*)(out + ((size_t)T_STEPS * BATCH + b) * HID + l * 4) = vs;
        float4 vc = make_float4(c, c, c, c);
        *(float4*)(out + ((size_t)T_STEPS * BATCH + BATCH + b) * HID + l * 4) = vc;
    }
}

extern "C" void kernel_launch(void* const* d_in, const int* in_sizes, int n_in,
                              void* d_out, int out_size) {
    const float* X  = (const float*)d_in[0];
    const float* Wf = (const float*)d_in[1];
    const float* bf = (const float*)d_in[2];
    const float* Wi = (const float*)d_in[3];
    const float* bi = (const float*)d_in[4];
    const float* Wu = (const float*)d_in[5];
    const float* bu = (const float*)d_in[6];
    const float* Wo = (const float*)d_in[7];
    const float* bo = (const float*)d_in[8];
    float* out = (float*)d_out;

    cudaFuncSetAttribute(gemm_kernel, cudaFuncAttributeMaxDynamicSharedMemorySize,
                         GEMM_SMEM_BYTES);

    init_kernel<<<1, 1024>>>(Wf, Wi, Wu, Wo);
    gemm_kernel<<<(T_STEPS * BATCH) / 128, 256, GEMM_SMEM_BYTES>>>(
        X, Wf, bf, Wi, bi, Wu, bu, Wo, bo);
    rnn_chunk_kernel<<<(BATCH * NCH) / 8, 256>>>(out);
}